// round 2
// baseline (speedup 1.0000x reference)
#include <cuda_runtime.h>
#include <stdint.h>

#define NUM_TOKENS 2048
#define HIDDEN     768
#define MAXW       20
#define NUM_CAND   40960
#define UNARY      1024
#define SPAN_DIM   2324     // 3*768 + 20
#define NTOP       512
#define NPAD       65536

typedef unsigned long long ull;

// ---------------- device scratch (no runtime allocation allowed) ----------------
__device__ float g_P[NUM_TOKENS * 3072];   // [tok][0:1024)=H1a, [1024:2048)=H1b, [2048:3072)=HD
__device__ float g_tok_att[NUM_TOKENS];
__device__ float g_prior[MAXW];
__device__ float g_Cw[MAXW * UNARY];
__device__ ull   g_keys[NPAD];
__device__ float g_scores[NUM_CAND];
__device__ int   g_sorted_se[NUM_CAND];
__device__ int   g_pidx[NTOP];

// ---------------- tok_att = hidden @ w_attn + b_attn ----------------
__global__ void tok_att_kernel(const float* __restrict__ hid,
                               const float* __restrict__ w,
                               const float* __restrict__ b) {
    int warp = (blockIdx.x * blockDim.x + threadIdx.x) >> 5;
    int lane = threadIdx.x & 31;
    if (warp >= NUM_TOKENS) return;
    float acc = 0.f;
    for (int k = lane; k < HIDDEN; k += 32)
        acc += hid[(size_t)warp * HIDDEN + k] * w[k];
    #pragma unroll
    for (int o = 16; o; o >>= 1) acc += __shfl_down_sync(0xffffffffu, acc, o);
    if (lane == 0) g_tok_att[warp] = acc + b[0];
}

// ---------------- width tables: Cw[w] = emb_width[w] @ W1[1536:1556],
//                  prior[w] = relu(ewp[w]@Wp1+bp1)@Wp2 + bp2 ----------------
__global__ void tables_kernel(const float* __restrict__ ew,
                              const float* __restrict__ ewp,
                              const float* __restrict__ W1,
                              const float* __restrict__ Wp1,
                              const float* __restrict__ bp1,
                              const float* __restrict__ Wp2,
                              const float* __restrict__ bp2) {
    int w = blockIdx.x;
    int tid = threadIdx.x;
    __shared__ float red[256];
    float local = 0.f;
    for (int u = tid; u < UNARY; u += 256) {
        float cw = 0.f, hp = 0.f;
        #pragma unroll
        for (int f = 0; f < MAXW; f++) {
            cw += ew [w * MAXW + f] * W1 [(size_t)(1536 + f) * UNARY + u];
            hp += ewp[w * MAXW + f] * Wp1[(size_t)f * UNARY + u];
        }
        g_Cw[w * UNARY + u] = cw;
        hp += bp1[u];
        hp = fmaxf(hp, 0.f);
        local += hp * Wp2[u];
    }
    red[tid] = local;
    __syncthreads();
    for (int s = 128; s; s >>= 1) {
        if (tid < s) red[tid] += red[tid + s];
        __syncthreads();
    }
    if (tid == 0) g_prior[w] = red[0] + bp2[0];
}

// ---------------- SGEMM: g_P = hidden(2048x768) @ Wcat(768x3072) ----------------
#define BM 128
#define BN 128
#define BK 16
__global__ __launch_bounds__(256) void sgemm_kernel(const float* __restrict__ A,
                                                    const float* __restrict__ W1) {
    __shared__ float As[BK][BM];
    __shared__ float Bs[BK][BN];
    int bm = blockIdx.y * BM, bn = blockIdx.x * BN;
    int tid = threadIdx.x;
    int tr = tid >> 4, tc = tid & 15;

    float acc[8][8];
    #pragma unroll
    for (int i = 0; i < 8; i++)
        #pragma unroll
        for (int j = 0; j < 8; j++) acc[i][j] = 0.f;

    int a_row = tid >> 2;              // 0..63
    int a_col = (tid & 3) << 2;        // 0,4,8,12
    int b_k   = tid >> 5;              // 0..7
    int b_n   = (tid & 31) << 2;       // 0..124

    // virtual Wcat column -> W1 row offset  (tiles never straddle segments: 1024%128==0)
    int n_global = bn + b_n;
    int seg_off = (n_global < 1024) ? 0 : (n_global < 2048 ? 768 : 1556);
    int col = n_global & 1023;

    for (int kt = 0; kt < HIDDEN; kt += BK) {
        #pragma unroll
        for (int r0 = 0; r0 < BM; r0 += 64) {
            float4 v = *reinterpret_cast<const float4*>(
                &A[(size_t)(bm + a_row + r0) * HIDDEN + kt + a_col]);
            As[a_col + 0][a_row + r0] = v.x;
            As[a_col + 1][a_row + r0] = v.y;
            As[a_col + 2][a_row + r0] = v.z;
            As[a_col + 3][a_row + r0] = v.w;
        }
        #pragma unroll
        for (int k0 = 0; k0 < BK; k0 += 8) {
            int k = kt + b_k + k0;
            float4 v = *reinterpret_cast<const float4*>(
                &W1[(size_t)(seg_off + k) * UNARY + col]);
            *reinterpret_cast<float4*>(&Bs[b_k + k0][b_n]) = v;
        }
        __syncthreads();
        #pragma unroll
        for (int kk = 0; kk < BK; kk++) {
            float ra[8], rb[8];
            #pragma unroll
            for (int i = 0; i < 8; i++) ra[i] = As[kk][tr * 8 + i];
            #pragma unroll
            for (int j = 0; j < 8; j++) rb[j] = Bs[kk][tc * 8 + j];
            #pragma unroll
            for (int i = 0; i < 8; i++)
                #pragma unroll
                for (int j = 0; j < 8; j++) acc[i][j] += ra[i] * rb[j];
        }
        __syncthreads();
    }
    #pragma unroll
    for (int i = 0; i < 8; i++)
        #pragma unroll
        for (int j = 0; j < 8; j += 4) {
            float4 v = make_float4(acc[i][j], acc[i][j + 1], acc[i][j + 2], acc[i][j + 3]);
            *reinterpret_cast<float4*>(
                &g_P[(size_t)(bm + tr * 8 + i) * 3072 + bn + tc * 8 + j]) = v;
        }
}

// ---------------- per-candidate: span_emb row + score + sort key ----------------
__global__ __launch_bounds__(256) void candidate_kernel(
    const float* __restrict__ hid,
    const int* __restrict__ starts,
    const int* __restrict__ ends,
    const float* __restrict__ ew,
    const float* __restrict__ b1,
    const float* __restrict__ W2,
    const float* __restrict__ b2v,
    float* __restrict__ out) {

    int c = blockIdx.x;
    int tid = threadIdx.x;
    int s = starts[c], e = ends[c];
    int wi = e - s;                    // 0..19

    __shared__ float p[32];
    __shared__ float red[256];

    // softmax over span tokens (warp 0)
    if (tid < 32) {
        float l = (tid <= wi) ? g_tok_att[s + tid] : __int_as_float(0xff800000); // -inf
        float m = l;
        #pragma unroll
        for (int o = 16; o; o >>= 1) m = fmaxf(m, __shfl_xor_sync(0xffffffffu, m, o));
        float ex = (tid <= wi) ? expf(l - m) : 0.f;
        float sm = ex;
        #pragma unroll
        for (int o = 16; o; o >>= 1) sm += __shfl_xor_sync(0xffffffffu, sm, o);
        p[tid] = ex / sm;
    }
    __syncthreads();

    float* row = out + (size_t)c * SPAN_DIM;
    for (int d = tid; d < HIDDEN; d += 256) {
        row[d]          = hid[(size_t)s * HIDDEN + d];
        row[HIDDEN + d] = hid[(size_t)e * HIDDEN + d];
        float acc = 0.f;
        for (int i = 0; i <= wi; i++)
            acc += p[i] * hid[(size_t)(s + i) * HIDDEN + d];
        row[1556 + d] = acc;
    }
    if (tid < MAXW) row[1536 + tid] = ew[wi * MAXW + tid];

    // score = relu(H1a[s] + H1b[e] + Cw[wi] + sum_i p_i*HD[t_i] + b1) . W2 + b2 + prior[wi]
    float local = 0.f;
    for (int u = tid; u < UNARY; u += 256) {
        float pre = g_P[(size_t)s * 3072 + u]
                  + g_P[(size_t)e * 3072 + 1024 + u]
                  + g_Cw[wi * UNARY + u]
                  + b1[u];
        for (int i = 0; i <= wi; i++)
            pre += p[i] * g_P[(size_t)(s + i) * 3072 + 2048 + u];
        local += fmaxf(pre, 0.f) * W2[u];
    }
    red[tid] = local;
    __syncthreads();
    for (int st = 128; st; st >>= 1) {
        if (tid < st) red[tid] += red[tid + st];
        __syncthreads();
    }
    if (tid == 0) {
        float sc = red[0] + b2v[0] + g_prior[wi];
        g_scores[c] = sc;
        unsigned u = __float_as_uint(sc);
        u = (u & 0x80000000u) ? ~u : (u | 0x80000000u);  // ascending-orderable
        g_keys[c] = ((ull)(~u) << 32) | (unsigned)c;     // descending score, ties: idx asc
    }
}

__global__ void pad_keys() {
    int i = NUM_CAND + blockIdx.x * blockDim.x + threadIdx.x;
    if (i < NPAD) g_keys[i] = ~0ull;
}

// ---------------- bitonic sort (ascending, u64 keys) ----------------
__global__ __launch_bounds__(1024) void bitonic_smem_full() {
    __shared__ ull sk[2048];
    int base = blockIdx.x * 2048, t = threadIdx.x;
    sk[t] = g_keys[base + t];
    sk[t + 1024] = g_keys[base + t + 1024];
    __syncthreads();
    for (int k = 2; k <= 2048; k <<= 1)
        for (int j = k >> 1; j > 0; j >>= 1) {
            int i = ((t & ~(j - 1)) << 1) | (t & (j - 1));
            bool dir = (((base + i) & k) == 0);
            ull a = sk[i], b = sk[i | j];
            if ((a > b) == dir) { sk[i] = b; sk[i | j] = a; }
            __syncthreads();
        }
    g_keys[base + t] = sk[t];
    g_keys[base + t + 1024] = sk[t + 1024];
}

__global__ __launch_bounds__(1024) void bitonic_smem_tail(int k) {
    __shared__ ull sk[2048];
    int base = blockIdx.x * 2048, t = threadIdx.x;
    sk[t] = g_keys[base + t];
    sk[t + 1024] = g_keys[base + t + 1024];
    __syncthreads();
    for (int j = 1024; j > 0; j >>= 1) {
        int i = ((t & ~(j - 1)) << 1) | (t & (j - 1));
        bool dir = (((base + i) & k) == 0);
        ull a = sk[i], b = sk[i | j];
        if ((a > b) == dir) { sk[i] = b; sk[i | j] = a; }
        __syncthreads();
    }
    g_keys[base + t] = sk[t];
    g_keys[base + t + 1024] = sk[t + 1024];
}

__global__ void bitonic_gstep(int j, int k) {
    int pI = blockIdx.x * blockDim.x + threadIdx.x;   // 32768 pairs
    int i = ((pI & ~(j - 1)) << 1) | (pI & (j - 1));
    bool dir = ((i & k) == 0);
    ull a = g_keys[i], b = g_keys[i | j];
    if ((a > b) == dir) { g_keys[i] = b; g_keys[i | j] = a; }
}

__global__ void decorate_kernel(const int* __restrict__ starts,
                                const int* __restrict__ ends) {
    int pI = blockIdx.x * blockDim.x + threadIdx.x;
    if (pI < NUM_CAND) {
        int idx = (int)(g_keys[pI] & 0xffffffffull);
        g_sorted_se[pI] = (starts[idx] << 16) | ends[idx];
    }
}

// ---------------- serial greedy NMS + position sort + scalar outputs ----------------
__global__ __launch_bounds__(256) void nms_kernel(const int* __restrict__ starts,
                                                  const int* __restrict__ ends,
                                                  const int* __restrict__ spk,
                                                  float* __restrict__ out) {
    __shared__ int latest[NUM_TOKENS];
    __shared__ int earliest[NUM_TOKENS];
    __shared__ int chunk[2048];
    __shared__ ull akey[NTOP];
    __shared__ int aidx[NTOP];
    __shared__ int s_count;

    int tid = threadIdx.x, lane = tid & 31;
    for (int t = tid; t < NUM_TOKENS; t += 256) { latest[t] = -1; earliest[t] = NUM_TOKENS; }
    if (tid == 0) s_count = 0;
    __syncthreads();

    int count = 0, pos = 0;
    while (pos < NUM_CAND && count < NTOP) {
        int n = min(2048, NUM_CAND - pos);
        for (int t = tid; t < n; t += 256) chunk[t] = g_sorted_se[pos + t];
        __syncthreads();
        if (tid < 32) {
            for (int cI = 0; cI < n && count < NTOP; cI++) {
                int se = chunk[cI];
                int s = se >> 16, e = se & 0xffff;
                int t = s + lane;
                bool act = (lane <= e - s);
                bool c1 = act && (t > s) && (latest[t] > e);
                bool c2 = act && (t < e) && (earliest[t] < s);
                if (__ballot_sync(0xffffffffu, c1 || c2) == 0u) {
                    if (lane == 0) {
                        latest[s] = max(latest[s], e);
                        earliest[e] = min(earliest[e], s);
                        int idx = (int)(g_keys[pos + cI] & 0xffffffffull);
                        aidx[count] = idx;
                        // stable (start,end) key with acceptance rank as tiebreak
                        akey[count] = (((ull)(s * (NUM_TOKENS + 1) + e)) << 10) | (unsigned)count;
                    }
                    count++;
                }
                __syncwarp();
            }
            if (lane == 0) s_count = count;
        }
        __syncthreads();
        count = s_count;
        pos += n;
    }
    __syncthreads();
    for (int r = tid; r < NTOP; r += 256)
        if (r >= count) { akey[r] = ~0ull; aidx[r] = 0; }
    __syncthreads();

    // block bitonic sort of 512 (key asc = (start,end,rank) asc), payload aidx
    for (int k = 2; k <= NTOP; k <<= 1)
        for (int j = k >> 1; j > 0; j >>= 1) {
            int i = ((tid & ~(j - 1)) << 1) | (tid & (j - 1));   // tid<256 -> 256 pairs
            bool dir = ((i & k) == 0);
            ull a = akey[i], b = akey[i | j];
            if ((a > b) == dir) {
                akey[i] = b; akey[i | j] = a;
                int x = aidx[i]; aidx[i] = aidx[i | j]; aidx[i | j] = x;
            }
            __syncthreads();
        }

    int first = aidx[0];
    const size_t base = (size_t)NUM_CAND * SPAN_DIM;
    const size_t emb_off = base + 3 * NTOP;
    const size_t sc_off = emb_off + (size_t)NTOP * SPAN_DIM;
    for (int r = tid; r < NTOP; r += 256) {
        int idx = (r < count) ? aidx[r] : first;
        int s = starts[idx], e = ends[idx];
        out[base + r]            = (float)idx;
        out[base + NTOP + r]     = (float)s;
        out[base + 2 * NTOP + r] = (float)e;
        out[sc_off + r]          = g_scores[idx];
        out[sc_off + NTOP + r]   = (float)spk[s];
        g_pidx[r] = idx;
    }
}

__global__ void gather_emb(float* __restrict__ out) {
    int r = blockIdx.x;
    int idx = g_pidx[r];
    const float* src = out + (size_t)idx * SPAN_DIM;
    float* dst = out + (size_t)NUM_CAND * SPAN_DIM + 3 * NTOP + (size_t)r * SPAN_DIM;
    for (int d = threadIdx.x; d < SPAN_DIM; d += 256) dst[d] = src[d];
}

// ---------------- launch ----------------
extern "C" void kernel_launch(void* const* d_in, const int* in_sizes, int n_in,
                              void* d_out, int out_size) {
    const float* hid    = (const float*)d_in[0];
    const int*   starts = (const int*)  d_in[1];
    const int*   ends   = (const int*)  d_in[2];
    const int*   spk    = (const int*)  d_in[3];
    const float* w_attn = (const float*)d_in[4];
    const float* b_attn = (const float*)d_in[5];
    const float* W1     = (const float*)d_in[6];
    const float* b1     = (const float*)d_in[7];
    const float* W2     = (const float*)d_in[8];
    const float* b2     = (const float*)d_in[9];
    const float* ew     = (const float*)d_in[10];
    const float* ewp    = (const float*)d_in[11];
    const float* Wp1    = (const float*)d_in[12];
    const float* bp1    = (const float*)d_in[13];
    const float* Wp2    = (const float*)d_in[14];
    const float* bp2    = (const float*)d_in[15];
    float* out = (float*)d_out;

    tok_att_kernel<<<256, 256>>>(hid, w_attn, b_attn);
    tables_kernel<<<20, 256>>>(ew, ewp, W1, Wp1, bp1, Wp2, bp2);
    sgemm_kernel<<<dim3(24, 16), 256>>>(hid, W1);
    pad_keys<<<100, 256>>>();
    candidate_kernel<<<NUM_CAND, 256>>>(hid, starts, ends, ew, b1, W2, b2, out);

    bitonic_smem_full<<<32, 1024>>>();
    for (int k = 4096; k <= 65536; k <<= 1) {
        for (int j = k >> 1; j >= 2048; j >>= 1)
            bitonic_gstep<<<128, 256>>>(j, k);
        bitonic_smem_tail<<<32, 1024>>>(k);
    }
    decorate_kernel<<<160, 256>>>(starts, ends);
    nms_kernel<<<1, 256>>>(starts, ends, spk, out);
    gather_emb<<<NTOP, 256>>>(out);
}

// round 3
// speedup vs baseline: 1.1210x; 1.1210x over previous
#include <cuda_runtime.h>
#include <stdint.h>

#define NUM_TOKENS 2048
#define HIDDEN     768
#define MAXW       20
#define NUM_CAND   40960
#define UNARY      1024
#define SPAN_DIM   2324     // 3*768 + 20
#define NTOP       512
#define NPAD       65536

typedef unsigned long long ull;

// ---------------- device scratch ----------------
__device__ float g_P[NUM_TOKENS * 3072];   // [tok][0:1024)=H1a, [1024:2048)=H1b, [2048:3072)=HD
__device__ float g_tok_att[NUM_TOKENS];
__device__ float g_prior[MAXW];
__device__ float g_Cw[MAXW * UNARY];
__device__ float g_probs[NUM_CAND * MAXW];
__device__ ull   g_keys[NPAD];
__device__ float g_scores[NUM_CAND];
__device__ int   g_sorted_se[NUM_CAND];
__device__ int   g_pidx[NTOP];

// ---------------- tok_att = hidden @ w_attn + b_attn ----------------
__global__ void tok_att_kernel(const float* __restrict__ hid,
                               const float* __restrict__ w,
                               const float* __restrict__ b) {
    int warp = (blockIdx.x * blockDim.x + threadIdx.x) >> 5;
    int lane = threadIdx.x & 31;
    if (warp >= NUM_TOKENS) return;
    float acc = 0.f;
    for (int k = lane; k < HIDDEN; k += 32)
        acc += hid[(size_t)warp * HIDDEN + k] * w[k];
    #pragma unroll
    for (int o = 16; o; o >>= 1) acc += __shfl_down_sync(0xffffffffu, acc, o);
    if (lane == 0) g_tok_att[warp] = acc + b[0];
}

// ---------------- width tables ----------------
__global__ void tables_kernel(const float* __restrict__ ew,
                              const float* __restrict__ ewp,
                              const float* __restrict__ W1,
                              const float* __restrict__ Wp1,
                              const float* __restrict__ bp1,
                              const float* __restrict__ Wp2,
                              const float* __restrict__ bp2) {
    int w = blockIdx.x;
    int tid = threadIdx.x;
    __shared__ float red[256];
    float local = 0.f;
    for (int u = tid; u < UNARY; u += 256) {
        float cw = 0.f, hp = 0.f;
        #pragma unroll
        for (int f = 0; f < MAXW; f++) {
            cw += ew [w * MAXW + f] * W1 [(size_t)(1536 + f) * UNARY + u];
            hp += ewp[w * MAXW + f] * Wp1[(size_t)f * UNARY + u];
        }
        g_Cw[w * UNARY + u] = cw;
        hp += bp1[u];
        hp = fmaxf(hp, 0.f);
        local += hp * Wp2[u];
    }
    red[tid] = local;
    __syncthreads();
    for (int s = 128; s; s >>= 1) {
        if (tid < s) red[tid] += red[tid + s];
        __syncthreads();
    }
    if (tid == 0) g_prior[w] = red[0] + bp2[0];
}

// ---------------- SGEMM: g_P = hidden(2048x768) @ Wcat(768x3072), double-buffered ----------------
#define BM 128
#define BN 128
#define BK 16
__global__ __launch_bounds__(256) void sgemm_kernel(const float* __restrict__ A,
                                                    const float* __restrict__ W1) {
    __shared__ float As[2][BK][BM];
    __shared__ float Bs[2][BK][BN];
    int bm = blockIdx.y * BM, bn = blockIdx.x * BN;
    int tid = threadIdx.x;
    int tr = tid >> 4, tc = tid & 15;

    float acc[8][8];
    #pragma unroll
    for (int i = 0; i < 8; i++)
        #pragma unroll
        for (int j = 0; j < 8; j++) acc[i][j] = 0.f;

    int a_row = tid >> 2;              // 0..63
    int a_col = (tid & 3) << 2;        // 0,4,8,12
    int b_k   = tid >> 5;              // 0..7
    int b_n   = (tid & 31) << 2;       // 0..124

    int n_global = bn + b_n;
    int seg_off = (n_global < 1024) ? 0 : (n_global < 2048 ? 768 : 1556);
    int col = n_global & 1023;

    float4 ra0, ra1, rb0, rb1;
    // prologue: load tile 0
    ra0 = *reinterpret_cast<const float4*>(&A[(size_t)(bm + a_row) * HIDDEN + a_col]);
    ra1 = *reinterpret_cast<const float4*>(&A[(size_t)(bm + a_row + 64) * HIDDEN + a_col]);
    rb0 = *reinterpret_cast<const float4*>(&W1[(size_t)(seg_off + b_k) * UNARY + col]);
    rb1 = *reinterpret_cast<const float4*>(&W1[(size_t)(seg_off + b_k + 8) * UNARY + col]);
    {
        As[0][a_col + 0][a_row] = ra0.x; As[0][a_col + 1][a_row] = ra0.y;
        As[0][a_col + 2][a_row] = ra0.z; As[0][a_col + 3][a_row] = ra0.w;
        As[0][a_col + 0][a_row + 64] = ra1.x; As[0][a_col + 1][a_row + 64] = ra1.y;
        As[0][a_col + 2][a_row + 64] = ra1.z; As[0][a_col + 3][a_row + 64] = ra1.w;
        *reinterpret_cast<float4*>(&Bs[0][b_k][b_n]) = rb0;
        *reinterpret_cast<float4*>(&Bs[0][b_k + 8][b_n]) = rb1;
    }
    __syncthreads();

    int buf = 0;
    for (int kt = 0; kt < HIDDEN; kt += BK) {
        bool more = (kt + BK) < HIDDEN;
        if (more) {
            int kn = kt + BK;
            ra0 = *reinterpret_cast<const float4*>(&A[(size_t)(bm + a_row) * HIDDEN + kn + a_col]);
            ra1 = *reinterpret_cast<const float4*>(&A[(size_t)(bm + a_row + 64) * HIDDEN + kn + a_col]);
            rb0 = *reinterpret_cast<const float4*>(&W1[(size_t)(seg_off + kn + b_k) * UNARY + col]);
            rb1 = *reinterpret_cast<const float4*>(&W1[(size_t)(seg_off + kn + b_k + 8) * UNARY + col]);
        }
        #pragma unroll
        for (int kk = 0; kk < BK; kk++) {
            float4 a0 = *reinterpret_cast<const float4*>(&As[buf][kk][tr * 8]);
            float4 a1 = *reinterpret_cast<const float4*>(&As[buf][kk][tr * 8 + 4]);
            float4 b0 = *reinterpret_cast<const float4*>(&Bs[buf][kk][tc * 8]);
            float4 b1v = *reinterpret_cast<const float4*>(&Bs[buf][kk][tc * 8 + 4]);
            float ra[8] = {a0.x, a0.y, a0.z, a0.w, a1.x, a1.y, a1.z, a1.w};
            float rb[8] = {b0.x, b0.y, b0.z, b0.w, b1v.x, b1v.y, b1v.z, b1v.w};
            #pragma unroll
            for (int i = 0; i < 8; i++)
                #pragma unroll
                for (int j = 0; j < 8; j++) acc[i][j] += ra[i] * rb[j];
        }
        if (more) {
            int nb = buf ^ 1;
            As[nb][a_col + 0][a_row] = ra0.x; As[nb][a_col + 1][a_row] = ra0.y;
            As[nb][a_col + 2][a_row] = ra0.z; As[nb][a_col + 3][a_row] = ra0.w;
            As[nb][a_col + 0][a_row + 64] = ra1.x; As[nb][a_col + 1][a_row + 64] = ra1.y;
            As[nb][a_col + 2][a_row + 64] = ra1.z; As[nb][a_col + 3][a_row + 64] = ra1.w;
            *reinterpret_cast<float4*>(&Bs[nb][b_k][b_n]) = rb0;
            *reinterpret_cast<float4*>(&Bs[nb][b_k + 8][b_n]) = rb1;
            __syncthreads();
            buf = nb;
        }
    }
    #pragma unroll
    for (int i = 0; i < 8; i++)
        #pragma unroll
        for (int j = 0; j < 8; j += 4) {
            float4 v = make_float4(acc[i][j], acc[i][j + 1], acc[i][j + 2], acc[i][j + 3]);
            *reinterpret_cast<float4*>(
                &g_P[(size_t)(bm + tr * 8 + i) * 3072 + bn + tc * 8 + j]) = v;
        }
}

// ---------------- softmax probs: one warp per candidate ----------------
__global__ __launch_bounds__(256) void p_kernel(const int* __restrict__ starts,
                                                const int* __restrict__ ends) {
    int c = blockIdx.x * 8 + (threadIdx.x >> 5);
    int lane = threadIdx.x & 31;
    if (c >= NUM_CAND) return;
    int s = starts[c], e = ends[c];
    int wi = e - s;
    float l = (lane <= wi) ? g_tok_att[s + lane] : __int_as_float(0xff800000);
    float m = l;
    #pragma unroll
    for (int o = 16; o; o >>= 1) m = fmaxf(m, __shfl_xor_sync(0xffffffffu, m, o));
    float ex = (lane <= wi) ? expf(l - m) : 0.f;
    float sm = ex;
    #pragma unroll
    for (int o = 16; o; o >>= 1) sm += __shfl_xor_sync(0xffffffffu, sm, o);
    if (lane < MAXW) g_probs[c * MAXW + lane] = (lane <= wi) ? (ex / sm) : 0.f;
}

// ---------------- span_emb rows (streaming stores, bypass L2) ----------------
__global__ __launch_bounds__(192) void emb_kernel(const float* __restrict__ hid,
                                                  const int* __restrict__ starts,
                                                  const int* __restrict__ ends,
                                                  const float* __restrict__ ew,
                                                  float* __restrict__ out) {
    int c = blockIdx.x;
    int tid = threadIdx.x;
    int s = starts[c], e = ends[c];
    int wi = e - s;

    __shared__ float p[MAXW];
    if (tid < MAXW) p[tid] = g_probs[c * MAXW + tid];
    __syncthreads();

    float4* row4 = reinterpret_cast<float4*>(out + (size_t)c * SPAN_DIM);
    const float4* hid4 = reinterpret_cast<const float4*>(hid);

    float4 acc = make_float4(0.f, 0.f, 0.f, 0.f);
    for (int i = 0; i <= wi; i++) {
        float4 v = hid4[(size_t)(s + i) * 192 + tid];
        if (i == 0)  __stcs(&row4[tid], v);
        if (i == wi) __stcs(&row4[192 + tid], v);
        float pi = p[i];
        acc.x += pi * v.x; acc.y += pi * v.y; acc.z += pi * v.z; acc.w += pi * v.w;
    }
    __stcs(&row4[389 + tid], acc);
    if (tid < 5) {
        float4 w = reinterpret_cast<const float4*>(ew)[wi * 5 + tid];
        __stcs(&row4[384 + tid], w);
    }
}

// ---------------- score: one warp per candidate ----------------
__global__ __launch_bounds__(256) void score_kernel(const int* __restrict__ starts,
                                                    const int* __restrict__ ends,
                                                    const float* __restrict__ b1,
                                                    const float* __restrict__ W2,
                                                    const float* __restrict__ b2v) {
    int c = blockIdx.x * 8 + (threadIdx.x >> 5);
    int lane = threadIdx.x & 31;
    if (c >= NUM_CAND) return;
    int s = starts[c], e = ends[c];
    int wi = e - s;

    float pv = (lane <= wi) ? g_probs[c * MAXW + lane] : 0.f;

    const float4* pa  = reinterpret_cast<const float4*>(&g_P[(size_t)s * 3072]);
    const float4* pb  = reinterpret_cast<const float4*>(&g_P[(size_t)e * 3072 + 1024]);
    const float4* pcw = reinterpret_cast<const float4*>(&g_Cw[wi * UNARY]);
    const float4* pb1 = reinterpret_cast<const float4*>(b1);

    float4 acc[8];
    #pragma unroll
    for (int j = 0; j < 8; j++) {
        int idx = j * 32 + lane;
        float4 a = pa[idx], b = pb[idx], cw = pcw[idx], bb = pb1[idx];
        acc[j].x = a.x + b.x + cw.x + bb.x;
        acc[j].y = a.y + b.y + cw.y + bb.y;
        acc[j].z = a.z + b.z + cw.z + bb.z;
        acc[j].w = a.w + b.w + cw.w + bb.w;
    }
    for (int i = 0; i <= wi; i++) {
        float pi = __shfl_sync(0xffffffffu, pv, i);
        const float4* hd = reinterpret_cast<const float4*>(&g_P[(size_t)(s + i) * 3072 + 2048]);
        #pragma unroll
        for (int j = 0; j < 8; j++) {
            float4 v = hd[j * 32 + lane];
            acc[j].x += pi * v.x; acc[j].y += pi * v.y;
            acc[j].z += pi * v.z; acc[j].w += pi * v.w;
        }
    }
    const float4* W2_4 = reinterpret_cast<const float4*>(W2);
    float local = 0.f;
    #pragma unroll
    for (int j = 0; j < 8; j++) {
        float4 w = W2_4[j * 32 + lane];
        local += fmaxf(acc[j].x, 0.f) * w.x + fmaxf(acc[j].y, 0.f) * w.y
               + fmaxf(acc[j].z, 0.f) * w.z + fmaxf(acc[j].w, 0.f) * w.w;
    }
    #pragma unroll
    for (int o = 16; o; o >>= 1) local += __shfl_xor_sync(0xffffffffu, local, o);
    if (lane == 0) {
        float sc = local + b2v[0] + g_prior[wi];
        g_scores[c] = sc;
        unsigned u = __float_as_uint(sc);
        u = (u & 0x80000000u) ? ~u : (u | 0x80000000u);
        g_keys[c] = ((ull)(~u) << 32) | (unsigned)c;
    }
}

__global__ void pad_keys() {
    int i = NUM_CAND + blockIdx.x * blockDim.x + threadIdx.x;
    if (i < NPAD) g_keys[i] = ~0ull;
}

// ---------------- bitonic sort (ascending, u64 keys) ----------------
__global__ __launch_bounds__(1024) void bitonic_smem_full() {
    __shared__ ull sk[2048];
    int base = blockIdx.x * 2048, t = threadIdx.x;
    sk[t] = g_keys[base + t];
    sk[t + 1024] = g_keys[base + t + 1024];
    __syncthreads();
    for (int k = 2; k <= 2048; k <<= 1)
        for (int j = k >> 1; j > 0; j >>= 1) {
            int i = ((t & ~(j - 1)) << 1) | (t & (j - 1));
            bool dir = (((base + i) & k) == 0);
            ull a = sk[i], b = sk[i | j];
            if ((a > b) == dir) { sk[i] = b; sk[i | j] = a; }
            __syncthreads();
        }
    g_keys[base + t] = sk[t];
    g_keys[base + t + 1024] = sk[t + 1024];
}

__global__ __launch_bounds__(1024) void bitonic_smem_tail(int k) {
    __shared__ ull sk[2048];
    int base = blockIdx.x * 2048, t = threadIdx.x;
    sk[t] = g_keys[base + t];
    sk[t + 1024] = g_keys[base + t + 1024];
    __syncthreads();
    for (int j = 1024; j > 0; j >>= 1) {
        int i = ((t & ~(j - 1)) << 1) | (t & (j - 1));
        bool dir = (((base + i) & k) == 0);
        ull a = sk[i], b = sk[i | j];
        if ((a > b) == dir) { sk[i] = b; sk[i | j] = a; }
        __syncthreads();
    }
    g_keys[base + t] = sk[t];
    g_keys[base + t + 1024] = sk[t + 1024];
}

__global__ void bitonic_gstep(int j, int k) {
    int pI = blockIdx.x * blockDim.x + threadIdx.x;
    int i = ((pI & ~(j - 1)) << 1) | (pI & (j - 1));
    bool dir = ((i & k) == 0);
    ull a = g_keys[i], b = g_keys[i | j];
    if ((a > b) == dir) { g_keys[i] = b; g_keys[i | j] = a; }
}

__global__ void decorate_kernel(const int* __restrict__ starts,
                                const int* __restrict__ ends) {
    int pI = blockIdx.x * blockDim.x + threadIdx.x;
    if (pI < NUM_CAND) {
        int idx = (int)(g_keys[pI] & 0xffffffffull);
        g_sorted_se[pI] = (starts[idx] << 16) | ends[idx];
    }
}

// ---------------- serial greedy NMS + position sort + scalar outputs ----------------
__global__ __launch_bounds__(256) void nms_kernel(const int* __restrict__ starts,
                                                  const int* __restrict__ ends,
                                                  const int* __restrict__ spk,
                                                  float* __restrict__ out) {
    __shared__ int latest[NUM_TOKENS];
    __shared__ int earliest[NUM_TOKENS];
    __shared__ int chunk[2048];
    __shared__ ull akey[NTOP];
    __shared__ int aidx[NTOP];
    __shared__ int s_count;

    int tid = threadIdx.x, lane = tid & 31;
    for (int t = tid; t < NUM_TOKENS; t += 256) { latest[t] = -1; earliest[t] = NUM_TOKENS; }
    if (tid == 0) s_count = 0;
    __syncthreads();

    int count = 0, pos = 0;
    while (pos < NUM_CAND && count < NTOP) {
        int n = min(2048, NUM_CAND - pos);
        for (int t = tid; t < n; t += 256) chunk[t] = g_sorted_se[pos + t];
        __syncthreads();
        if (tid < 32) {
            for (int cI = 0; cI < n && count < NTOP; cI++) {
                int se = chunk[cI];
                int s = se >> 16, e = se & 0xffff;
                int t = s + lane;
                bool act = (lane <= e - s);
                bool c1 = act && (t > s) && (latest[t] > e);
                bool c2 = act && (t < e) && (earliest[t] < s);
                if (__ballot_sync(0xffffffffu, c1 || c2) == 0u) {
                    if (lane == 0) {
                        latest[s] = max(latest[s], e);
                        earliest[e] = min(earliest[e], s);
                        int idx = (int)(g_keys[pos + cI] & 0xffffffffull);
                        aidx[count] = idx;
                        akey[count] = (((ull)(s * (NUM_TOKENS + 1) + e)) << 10) | (unsigned)count;
                    }
                    count++;
                }
                __syncwarp();
            }
            if (lane == 0) s_count = count;
        }
        __syncthreads();
        count = s_count;
        pos += n;
    }
    __syncthreads();
    for (int r = tid; r < NTOP; r += 256)
        if (r >= count) { akey[r] = ~0ull; aidx[r] = 0; }
    __syncthreads();

    for (int k = 2; k <= NTOP; k <<= 1)
        for (int j = k >> 1; j > 0; j >>= 1) {
            int i = ((tid & ~(j - 1)) << 1) | (tid & (j - 1));
            bool dir = ((i & k) == 0);
            ull a = akey[i], b = akey[i | j];
            if ((a > b) == dir) {
                akey[i] = b; akey[i | j] = a;
                int x = aidx[i]; aidx[i] = aidx[i | j]; aidx[i | j] = x;
            }
            __syncthreads();
        }

    int first = aidx[0];
    const size_t base = (size_t)NUM_CAND * SPAN_DIM;
    const size_t emb_off = base + 3 * NTOP;
    const size_t sc_off = emb_off + (size_t)NTOP * SPAN_DIM;
    for (int r = tid; r < NTOP; r += 256) {
        int idx = (r < count) ? aidx[r] : first;
        int s = starts[idx], e = ends[idx];
        out[base + r]            = (float)idx;
        out[base + NTOP + r]     = (float)s;
        out[base + 2 * NTOP + r] = (float)e;
        out[sc_off + r]          = g_scores[idx];
        out[sc_off + NTOP + r]   = (float)spk[s];
        g_pidx[r] = idx;
    }
}

__global__ void gather_emb(float* __restrict__ out) {
    int r = blockIdx.x;
    int idx = g_pidx[r];
    const float* src = out + (size_t)idx * SPAN_DIM;
    float* dst = out + (size_t)NUM_CAND * SPAN_DIM + 3 * NTOP + (size_t)r * SPAN_DIM;
    for (int d = threadIdx.x; d < SPAN_DIM; d += 256) dst[d] = src[d];
}

// ---------------- launch ----------------
extern "C" void kernel_launch(void* const* d_in, const int* in_sizes, int n_in,
                              void* d_out, int out_size) {
    const float* hid    = (const float*)d_in[0];
    const int*   starts = (const int*)  d_in[1];
    const int*   ends   = (const int*)  d_in[2];
    const int*   spk    = (const int*)  d_in[3];
    const float* w_attn = (const float*)d_in[4];
    const float* b_attn = (const float*)d_in[5];
    const float* W1     = (const float*)d_in[6];
    const float* b1     = (const float*)d_in[7];
    const float* W2     = (const float*)d_in[8];
    const float* b2     = (const float*)d_in[9];
    const float* ew     = (const float*)d_in[10];
    const float* ewp    = (const float*)d_in[11];
    const float* Wp1    = (const float*)d_in[12];
    const float* bp1    = (const float*)d_in[13];
    const float* Wp2    = (const float*)d_in[14];
    const float* bp2    = (const float*)d_in[15];
    float* out = (float*)d_out;

    tok_att_kernel<<<256, 256>>>(hid, w_attn, b_attn);
    tables_kernel<<<20, 256>>>(ew, ewp, W1, Wp1, bp1, Wp2, bp2);
    pad_keys<<<100, 256>>>();
    sgemm_kernel<<<dim3(24, 16), 256>>>(hid, W1);
    p_kernel<<<NUM_CAND / 8, 256>>>(starts, ends);
    emb_kernel<<<NUM_CAND, 192>>>(hid, starts, ends, ew, out);
    score_kernel<<<NUM_CAND / 8, 256>>>(starts, ends, b1, W2, b2);

    bitonic_smem_full<<<32, 1024>>>();
    for (int k = 4096; k <= 65536; k <<= 1) {
        for (int j = k >> 1; j >= 2048; j >>= 1)
            bitonic_gstep<<<128, 256>>>(j, k);
        bitonic_smem_tail<<<32, 1024>>>(k);
    }
    decorate_kernel<<<160, 256>>>(starts, ends);
    nms_kernel<<<1, 256>>>(starts, ends, spk, out);
    gather_emb<<<NTOP, 256>>>(out);
}

// round 4
// speedup vs baseline: 1.2583x; 1.1224x over previous
#include <cuda_runtime.h>
#include <stdint.h>

#define NUM_TOKENS 2048
#define HIDDEN     768
#define MAXW       20
#define NUM_CAND   40960
#define UNARY      1024
#define SPAN_DIM   2324     // 3*768 + 20
#define NTOP       512
#define NPAD       65536

typedef unsigned long long ull;

// ---------------- device scratch ----------------
__device__ float g_P[NUM_TOKENS * 3072];   // [tok][0:1024)=H1a, [1024:2048)=H1b, [2048:3072)=HD
__device__ float g_tok_att[NUM_TOKENS];
__device__ float g_prior[MAXW];
__device__ float g_Cw[MAXW * UNARY];
__device__ float g_probs[NUM_CAND * MAXW];
__device__ ull   g_keys[NPAD];
__device__ float g_scores[NUM_CAND];
__device__ int   g_sorted_se[NUM_CAND];
__device__ int   g_pidx[NTOP];
__device__ int   g_hist[NUM_TOKENS];
__device__ int   g_base[NUM_TOKENS];
__device__ int   g_perm[NUM_CAND];

// ---------------- f32x2 packed helpers ----------------
__device__ __forceinline__ ull pack2(float lo, float hi) {
    ull r; asm("mov.b64 %0, {%1, %2};" : "=l"(r) : "f"(lo), "f"(hi)); return r;
}
__device__ __forceinline__ ull fma2(ull a, ull b, ull c) {
    ull d; asm("fma.rn.f32x2 %0, %1, %2, %3;" : "=l"(d) : "l"(a), "l"(b), "l"(c)); return d;
}
__device__ __forceinline__ float2 unpack2(ull v) {
    float2 f; asm("mov.b64 {%0, %1}, %2;" : "=f"(f.x), "=f"(f.y) : "l"(v)); return f;
}

// ---------------- tok_att = hidden @ w_attn + b_attn ----------------
__global__ void tok_att_kernel(const float* __restrict__ hid,
                               const float* __restrict__ w,
                               const float* __restrict__ b) {
    int warp = (blockIdx.x * blockDim.x + threadIdx.x) >> 5;
    int lane = threadIdx.x & 31;
    if (warp >= NUM_TOKENS) return;
    float acc = 0.f;
    for (int k = lane; k < HIDDEN; k += 32)
        acc += hid[(size_t)warp * HIDDEN + k] * w[k];
    #pragma unroll
    for (int o = 16; o; o >>= 1) acc += __shfl_down_sync(0xffffffffu, acc, o);
    if (lane == 0) g_tok_att[warp] = acc + b[0];
}

// ---------------- width tables ----------------
__global__ void tables_kernel(const float* __restrict__ ew,
                              const float* __restrict__ ewp,
                              const float* __restrict__ W1,
                              const float* __restrict__ Wp1,
                              const float* __restrict__ bp1,
                              const float* __restrict__ Wp2,
                              const float* __restrict__ bp2) {
    int w = blockIdx.x;
    int tid = threadIdx.x;
    __shared__ float red[256];
    float local = 0.f;
    for (int u = tid; u < UNARY; u += 256) {
        float cw = 0.f, hp = 0.f;
        #pragma unroll
        for (int f = 0; f < MAXW; f++) {
            cw += ew [w * MAXW + f] * W1 [(size_t)(1536 + f) * UNARY + u];
            hp += ewp[w * MAXW + f] * Wp1[(size_t)f * UNARY + u];
        }
        g_Cw[w * UNARY + u] = cw;
        hp += bp1[u];
        hp = fmaxf(hp, 0.f);
        local += hp * Wp2[u];
    }
    red[tid] = local;
    __syncthreads();
    for (int s = 128; s; s >>= 1) {
        if (tid < s) red[tid] += red[tid + s];
        __syncthreads();
    }
    if (tid == 0) g_prior[w] = red[0] + bp2[0];
}

// ---------------- counting-sort permutation by start ----------------
__global__ void hist_zero() { g_hist[blockIdx.x * 256 + threadIdx.x] = 0; }
__global__ void hist_kernel(const int* __restrict__ starts) {
    int c = blockIdx.x * 256 + threadIdx.x;
    if (c < NUM_CAND) atomicAdd(&g_hist[starts[c]], 1);
}
__global__ __launch_bounds__(1024) void scan_kernel() {
    __shared__ int a[2048], b[2048];
    int t = threadIdx.x;
    a[t] = g_hist[t]; a[t + 1024] = g_hist[t + 1024];
    __syncthreads();
    int* src = a; int* dst = b;
    for (int off = 1; off < 2048; off <<= 1) {
        #pragma unroll
        for (int q = 0; q < 2; q++) {
            int i = t + q * 1024;
            dst[i] = src[i] + (i >= off ? src[i - off] : 0);
        }
        __syncthreads();
        int* tmp = src; src = dst; dst = tmp;
    }
    g_base[t]        = t ? src[t - 1] : 0;
    g_base[t + 1024] = src[t + 1023];
}
__global__ void scatter_kernel(const int* __restrict__ starts) {
    int c = blockIdx.x * 256 + threadIdx.x;
    if (c < NUM_CAND) {
        int pos = atomicAdd(&g_base[starts[c]], 1);
        g_perm[pos] = c;
    }
}

// ---------------- SGEMM: g_P = hidden(2048x768) @ Wcat(768x3072), f32x2 + double-buffered ----------------
#define BM 128
#define BN 128
#define BK 16
__global__ __launch_bounds__(256, 2) void sgemm_kernel(const float* __restrict__ A,
                                                       const float* __restrict__ W1) {
    __shared__ float As[2][BK][BM];
    __shared__ float Bs[2][BK][BN];
    int bm = blockIdx.y * BM, bn = blockIdx.x * BN;
    int tid = threadIdx.x;
    int tr = tid >> 4, tc = tid & 15;

    ull accp[8][4];
    #pragma unroll
    for (int i = 0; i < 8; i++)
        #pragma unroll
        for (int j = 0; j < 4; j++) accp[i][j] = 0ull;

    int a_row = tid >> 2;              // 0..63
    int a_col = (tid & 3) << 2;        // 0,4,8,12
    int b_k   = tid >> 5;              // 0..7
    int b_n   = (tid & 31) << 2;       // 0..124

    int n_global = bn + b_n;
    int seg_off = (n_global < 1024) ? 0 : (n_global < 2048 ? 768 : 1556);
    int col = n_global & 1023;

    float4 ra0, ra1, rb0, rb1;
    ra0 = *reinterpret_cast<const float4*>(&A[(size_t)(bm + a_row) * HIDDEN + a_col]);
    ra1 = *reinterpret_cast<const float4*>(&A[(size_t)(bm + a_row + 64) * HIDDEN + a_col]);
    rb0 = *reinterpret_cast<const float4*>(&W1[(size_t)(seg_off + b_k) * UNARY + col]);
    rb1 = *reinterpret_cast<const float4*>(&W1[(size_t)(seg_off + b_k + 8) * UNARY + col]);
    {
        As[0][a_col + 0][a_row] = ra0.x; As[0][a_col + 1][a_row] = ra0.y;
        As[0][a_col + 2][a_row] = ra0.z; As[0][a_col + 3][a_row] = ra0.w;
        As[0][a_col + 0][a_row + 64] = ra1.x; As[0][a_col + 1][a_row + 64] = ra1.y;
        As[0][a_col + 2][a_row + 64] = ra1.z; As[0][a_col + 3][a_row + 64] = ra1.w;
        *reinterpret_cast<float4*>(&Bs[0][b_k][b_n]) = rb0;
        *reinterpret_cast<float4*>(&Bs[0][b_k + 8][b_n]) = rb1;
    }
    __syncthreads();

    int buf = 0;
    for (int kt = 0; kt < HIDDEN; kt += BK) {
        bool more = (kt + BK) < HIDDEN;
        if (more) {
            int kn = kt + BK;
            ra0 = *reinterpret_cast<const float4*>(&A[(size_t)(bm + a_row) * HIDDEN + kn + a_col]);
            ra1 = *reinterpret_cast<const float4*>(&A[(size_t)(bm + a_row + 64) * HIDDEN + kn + a_col]);
            rb0 = *reinterpret_cast<const float4*>(&W1[(size_t)(seg_off + kn + b_k) * UNARY + col]);
            rb1 = *reinterpret_cast<const float4*>(&W1[(size_t)(seg_off + kn + b_k + 8) * UNARY + col]);
        }
        #pragma unroll
        for (int kk = 0; kk < BK; kk++) {
            float4 a0 = *reinterpret_cast<const float4*>(&As[buf][kk][tr * 8]);
            float4 a1 = *reinterpret_cast<const float4*>(&As[buf][kk][tr * 8 + 4]);
            const ull* brow = reinterpret_cast<const ull*>(&Bs[buf][kk][tc * 8]);
            ull b0 = brow[0], b1v = brow[1], b2v = brow[2], b3v = brow[3];
            float ra[8] = {a0.x, a0.y, a0.z, a0.w, a1.x, a1.y, a1.z, a1.w};
            #pragma unroll
            for (int i = 0; i < 8; i++) {
                ull aa = pack2(ra[i], ra[i]);
                accp[i][0] = fma2(aa, b0,  accp[i][0]);
                accp[i][1] = fma2(aa, b1v, accp[i][1]);
                accp[i][2] = fma2(aa, b2v, accp[i][2]);
                accp[i][3] = fma2(aa, b3v, accp[i][3]);
            }
        }
        if (more) {
            int nb = buf ^ 1;
            As[nb][a_col + 0][a_row] = ra0.x; As[nb][a_col + 1][a_row] = ra0.y;
            As[nb][a_col + 2][a_row] = ra0.z; As[nb][a_col + 3][a_row] = ra0.w;
            As[nb][a_col + 0][a_row + 64] = ra1.x; As[nb][a_col + 1][a_row + 64] = ra1.y;
            As[nb][a_col + 2][a_row + 64] = ra1.z; As[nb][a_col + 3][a_row + 64] = ra1.w;
            *reinterpret_cast<float4*>(&Bs[nb][b_k][b_n]) = rb0;
            *reinterpret_cast<float4*>(&Bs[nb][b_k + 8][b_n]) = rb1;
            __syncthreads();
            buf = nb;
        }
    }
    #pragma unroll
    for (int i = 0; i < 8; i++) {
        float2 v0 = unpack2(accp[i][0]), v1 = unpack2(accp[i][1]);
        float2 v2 = unpack2(accp[i][2]), v3 = unpack2(accp[i][3]);
        float4 w0 = make_float4(v0.x, v0.y, v1.x, v1.y);
        float4 w1 = make_float4(v2.x, v2.y, v3.x, v3.y);
        size_t rowoff = (size_t)(bm + tr * 8 + i) * 3072 + bn + tc * 8;
        *reinterpret_cast<float4*>(&g_P[rowoff])     = w0;
        *reinterpret_cast<float4*>(&g_P[rowoff + 4]) = w1;
    }
}

// ---------------- softmax probs: one warp per candidate ----------------
__global__ __launch_bounds__(256) void p_kernel(const int* __restrict__ starts,
                                                const int* __restrict__ ends) {
    int c = blockIdx.x * 8 + (threadIdx.x >> 5);
    int lane = threadIdx.x & 31;
    if (c >= NUM_CAND) return;
    int s = starts[c], e = ends[c];
    int wi = e - s;
    float l = (lane <= wi) ? g_tok_att[s + lane] : __int_as_float(0xff800000);
    float m = l;
    #pragma unroll
    for (int o = 16; o; o >>= 1) m = fmaxf(m, __shfl_xor_sync(0xffffffffu, m, o));
    float ex = (lane <= wi) ? expf(l - m) : 0.f;
    float sm = ex;
    #pragma unroll
    for (int o = 16; o; o >>= 1) sm += __shfl_xor_sync(0xffffffffu, sm, o);
    if (lane < MAXW) g_probs[c * MAXW + lane] = (lane <= wi) ? (ex / sm) : 0.f;
}

// ---------------- span_emb rows (perm order, streaming stores) ----------------
__global__ __launch_bounds__(192) void emb_kernel(const float* __restrict__ hid,
                                                  const int* __restrict__ starts,
                                                  const int* __restrict__ ends,
                                                  const float* __restrict__ ew,
                                                  float* __restrict__ out) {
    int c = g_perm[blockIdx.x];
    int tid = threadIdx.x;
    int s = starts[c], e = ends[c];
    int wi = e - s;

    __shared__ float p[MAXW];
    if (tid < MAXW) p[tid] = g_probs[c * MAXW + tid];
    __syncthreads();

    float4* row4 = reinterpret_cast<float4*>(out + (size_t)c * SPAN_DIM);
    const float4* hid4 = reinterpret_cast<const float4*>(hid);

    float4 acc = make_float4(0.f, 0.f, 0.f, 0.f);
    for (int i = 0; i <= wi; i++) {
        float4 v = hid4[(size_t)(s + i) * 192 + tid];
        if (i == 0)  __stcs(&row4[tid], v);
        if (i == wi) __stcs(&row4[192 + tid], v);
        float pi = p[i];
        acc.x += pi * v.x; acc.y += pi * v.y; acc.z += pi * v.z; acc.w += pi * v.w;
    }
    __stcs(&row4[389 + tid], acc);
    if (tid < 5) {
        float4 w = reinterpret_cast<const float4*>(ew)[wi * 5 + tid];
        __stcs(&row4[384 + tid], w);
    }
}

// ---------------- score: one warp per candidate, perm order ----------------
__global__ __launch_bounds__(256) void score_kernel(const int* __restrict__ starts,
                                                    const int* __restrict__ ends,
                                                    const float* __restrict__ b1,
                                                    const float* __restrict__ W2,
                                                    const float* __restrict__ b2v) {
    int slot = blockIdx.x * 8 + (threadIdx.x >> 5);
    int lane = threadIdx.x & 31;
    if (slot >= NUM_CAND) return;
    int c = g_perm[slot];
    int s = starts[c], e = ends[c];
    int wi = e - s;

    float pv = (lane <= wi) ? g_probs[c * MAXW + lane] : 0.f;

    const float4* pa  = reinterpret_cast<const float4*>(&g_P[(size_t)s * 3072]);
    const float4* pb  = reinterpret_cast<const float4*>(&g_P[(size_t)e * 3072 + 1024]);
    const float4* pcw = reinterpret_cast<const float4*>(&g_Cw[wi * UNARY]);
    const float4* pb1 = reinterpret_cast<const float4*>(b1);

    float4 acc[8];
    #pragma unroll
    for (int j = 0; j < 8; j++) {
        int idx = j * 32 + lane;
        float4 a = pa[idx], b = pb[idx], cw = pcw[idx], bb = pb1[idx];
        acc[j].x = a.x + b.x + cw.x + bb.x;
        acc[j].y = a.y + b.y + cw.y + bb.y;
        acc[j].z = a.z + b.z + cw.z + bb.z;
        acc[j].w = a.w + b.w + cw.w + bb.w;
    }
    for (int i = 0; i <= wi; i++) {
        float pi = __shfl_sync(0xffffffffu, pv, i);
        const float4* hd = reinterpret_cast<const float4*>(&g_P[(size_t)(s + i) * 3072 + 2048]);
        #pragma unroll
        for (int j = 0; j < 8; j++) {
            float4 v = hd[j * 32 + lane];
            acc[j].x += pi * v.x; acc[j].y += pi * v.y;
            acc[j].z += pi * v.z; acc[j].w += pi * v.w;
        }
    }
    const float4* W2_4 = reinterpret_cast<const float4*>(W2);
    float local = 0.f;
    #pragma unroll
    for (int j = 0; j < 8; j++) {
        float4 w = W2_4[j * 32 + lane];
        local += fmaxf(acc[j].x, 0.f) * w.x + fmaxf(acc[j].y, 0.f) * w.y
               + fmaxf(acc[j].z, 0.f) * w.z + fmaxf(acc[j].w, 0.f) * w.w;
    }
    #pragma unroll
    for (int o = 16; o; o >>= 1) local += __shfl_xor_sync(0xffffffffu, local, o);
    if (lane == 0) {
        float sc = local + b2v[0] + g_prior[wi];
        g_scores[c] = sc;
        unsigned u = __float_as_uint(sc);
        u = (u & 0x80000000u) ? ~u : (u | 0x80000000u);
        g_keys[c] = ((ull)(~u) << 32) | (unsigned)c;
    }
}

__global__ void pad_keys() {
    int i = NUM_CAND + blockIdx.x * blockDim.x + threadIdx.x;
    if (i < NPAD) g_keys[i] = ~0ull;
}

// ---------------- bitonic sort, 4096-element smem chunks ----------------
__global__ __launch_bounds__(1024) void bitonic_smem_full4k() {
    __shared__ ull sk[4096];
    int base = blockIdx.x * 4096, t = threadIdx.x;
    #pragma unroll
    for (int r = 0; r < 4; r++) sk[t + r * 1024] = g_keys[base + t + r * 1024];
    __syncthreads();
    for (int k = 2; k <= 4096; k <<= 1)
        for (int j = k >> 1; j > 0; j >>= 1) {
            #pragma unroll
            for (int q = 0; q < 2; q++) {
                int pI = t + q * 1024;
                int i = ((pI & ~(j - 1)) << 1) | (pI & (j - 1));
                bool dir = (((base + i) & k) == 0);
                ull a = sk[i], b = sk[i | j];
                if ((a > b) == dir) { sk[i] = b; sk[i | j] = a; }
            }
            __syncthreads();
        }
    #pragma unroll
    for (int r = 0; r < 4; r++) g_keys[base + t + r * 1024] = sk[t + r * 1024];
}

__global__ __launch_bounds__(1024) void bitonic_smem_tail4k(int k) {
    __shared__ ull sk[4096];
    int base = blockIdx.x * 4096, t = threadIdx.x;
    #pragma unroll
    for (int r = 0; r < 4; r++) sk[t + r * 1024] = g_keys[base + t + r * 1024];
    __syncthreads();
    for (int j = 2048; j > 0; j >>= 1) {
        #pragma unroll
        for (int q = 0; q < 2; q++) {
            int pI = t + q * 1024;
            int i = ((pI & ~(j - 1)) << 1) | (pI & (j - 1));
            bool dir = (((base + i) & k) == 0);
            ull a = sk[i], b = sk[i | j];
            if ((a > b) == dir) { sk[i] = b; sk[i | j] = a; }
        }
        __syncthreads();
    }
    #pragma unroll
    for (int r = 0; r < 4; r++) g_keys[base + t + r * 1024] = sk[t + r * 1024];
}

__global__ void bitonic_gstep(int j, int k) {
    int pI = blockIdx.x * blockDim.x + threadIdx.x;
    int i = ((pI & ~(j - 1)) << 1) | (pI & (j - 1));
    bool dir = ((i & k) == 0);
    ull a = g_keys[i], b = g_keys[i | j];
    if ((a > b) == dir) { g_keys[i] = b; g_keys[i | j] = a; }
}

__global__ void decorate_kernel(const int* __restrict__ starts,
                                const int* __restrict__ ends) {
    int pI = blockIdx.x * blockDim.x + threadIdx.x;
    if (pI < NUM_CAND) {
        int idx = (int)(g_keys[pI] & 0xffffffffull);
        g_sorted_se[pI] = (starts[idx] << 16) | ends[idx];
    }
}

// ---------------- serial greedy NMS + position sort + scalar outputs ----------------
__global__ __launch_bounds__(256) void nms_kernel(const int* __restrict__ starts,
                                                  const int* __restrict__ ends,
                                                  const int* __restrict__ spk,
                                                  float* __restrict__ out) {
    __shared__ int latest[NUM_TOKENS];
    __shared__ int earliest[NUM_TOKENS];
    __shared__ int chunk[2048];
    __shared__ ull akey[NTOP];
    __shared__ int aidx[NTOP];
    __shared__ int s_count;

    int tid = threadIdx.x, lane = tid & 31;
    for (int t = tid; t < NUM_TOKENS; t += 256) { latest[t] = -1; earliest[t] = NUM_TOKENS; }
    if (tid == 0) s_count = 0;
    __syncthreads();

    int count = 0, pos = 0;
    while (pos < NUM_CAND && count < NTOP) {
        int n = min(2048, NUM_CAND - pos);
        for (int t = tid; t < n; t += 256) chunk[t] = g_sorted_se[pos + t];
        __syncthreads();
        if (tid < 32) {
            for (int cI = 0; cI < n && count < NTOP; cI++) {
                int se = chunk[cI];
                int s = se >> 16, e = se & 0xffff;
                int t = s + lane;
                bool act = (lane <= e - s);
                bool c1 = act && (t > s) && (latest[t] > e);
                bool c2 = act && (t < e) && (earliest[t] < s);
                if (__ballot_sync(0xffffffffu, c1 || c2) == 0u) {
                    if (lane == 0) {
                        latest[s] = max(latest[s], e);
                        earliest[e] = min(earliest[e], s);
                        int idx = (int)(g_keys[pos + cI] & 0xffffffffull);
                        aidx[count] = idx;
                        akey[count] = (((ull)(s * (NUM_TOKENS + 1) + e)) << 10) | (unsigned)count;
                    }
                    count++;
                }
                __syncwarp();
            }
            if (lane == 0) s_count = count;
        }
        __syncthreads();
        count = s_count;
        pos += n;
    }
    __syncthreads();
    for (int r = tid; r < NTOP; r += 256)
        if (r >= count) { akey[r] = ~0ull; aidx[r] = 0; }
    __syncthreads();

    for (int k = 2; k <= NTOP; k <<= 1)
        for (int j = k >> 1; j > 0; j >>= 1) {
            int i = ((tid & ~(j - 1)) << 1) | (tid & (j - 1));
            bool dir = ((i & k) == 0);
            ull a = akey[i], b = akey[i | j];
            if ((a > b) == dir) {
                akey[i] = b; akey[i | j] = a;
                int x = aidx[i]; aidx[i] = aidx[i | j]; aidx[i | j] = x;
            }
            __syncthreads();
        }

    int first = aidx[0];
    const size_t base = (size_t)NUM_CAND * SPAN_DIM;
    const size_t emb_off = base + 3 * NTOP;
    const size_t sc_off = emb_off + (size_t)NTOP * SPAN_DIM;
    for (int r = tid; r < NTOP; r += 256) {
        int idx = (r < count) ? aidx[r] : first;
        int s = starts[idx], e = ends[idx];
        out[base + r]            = (float)idx;
        out[base + NTOP + r]     = (float)s;
        out[base + 2 * NTOP + r] = (float)e;
        out[sc_off + r]          = g_scores[idx];
        out[sc_off + NTOP + r]   = (float)spk[s];
        g_pidx[r] = idx;
    }
}

__global__ void gather_emb(float* __restrict__ out) {
    int r = blockIdx.x;
    int idx = g_pidx[r];
    const float* src = out + (size_t)idx * SPAN_DIM;
    float* dst = out + (size_t)NUM_CAND * SPAN_DIM + 3 * NTOP + (size_t)r * SPAN_DIM;
    for (int d = threadIdx.x; d < SPAN_DIM; d += 256) dst[d] = src[d];
}

// ---------------- launch ----------------
extern "C" void kernel_launch(void* const* d_in, const int* in_sizes, int n_in,
                              void* d_out, int out_size) {
    const float* hid    = (const float*)d_in[0];
    const int*   starts = (const int*)  d_in[1];
    const int*   ends   = (const int*)  d_in[2];
    const int*   spk    = (const int*)  d_in[3];
    const float* w_attn = (const float*)d_in[4];
    const float* b_attn = (const float*)d_in[5];
    const float* W1     = (const float*)d_in[6];
    const float* b1     = (const float*)d_in[7];
    const float* W2     = (const float*)d_in[8];
    const float* b2     = (const float*)d_in[9];
    const float* ew     = (const float*)d_in[10];
    const float* ewp    = (const float*)d_in[11];
    const float* Wp1    = (const float*)d_in[12];
    const float* bp1    = (const float*)d_in[13];
    const float* Wp2    = (const float*)d_in[14];
    const float* bp2    = (const float*)d_in[15];
    float* out = (float*)d_out;

    tok_att_kernel<<<256, 256>>>(hid, w_attn, b_attn);
    tables_kernel<<<20, 256>>>(ew, ewp, W1, Wp1, bp1, Wp2, bp2);
    pad_keys<<<100, 256>>>();
    hist_zero<<<8, 256>>>();
    hist_kernel<<<160, 256>>>(starts);
    scan_kernel<<<1, 1024>>>();
    scatter_kernel<<<160, 256>>>(starts);
    sgemm_kernel<<<dim3(24, 16), 256>>>(hid, W1);
    p_kernel<<<NUM_CAND / 8, 256>>>(starts, ends);
    emb_kernel<<<NUM_CAND, 192>>>(hid, starts, ends, ew, out);
    score_kernel<<<NUM_CAND / 8, 256>>>(starts, ends, b1, W2, b2);

    bitonic_smem_full4k<<<16, 1024>>>();
    for (int k = 8192; k <= 65536; k <<= 1) {
        for (int j = k >> 1; j >= 4096; j >>= 1)
            bitonic_gstep<<<128, 256>>>(j, k);
        bitonic_smem_tail4k<<<16, 1024>>>(k);
    }
    decorate_kernel<<<160, 256>>>(starts, ends);
    nms_kernel<<<1, 256>>>(starts, ends, spk, out);
    gather_emb<<<NTOP, 256>>>(out);
}

// round 5
// speedup vs baseline: 1.3547x; 1.0766x over previous
#include <cuda_runtime.h>
#include <stdint.h>

#define NUM_TOKENS 2048
#define HIDDEN     768
#define MAXW       20
#define NUM_CAND   40960
#define UNARY      1024
#define SPAN_DIM   2324     // 3*768 + 20
#define NTOP       512
#define NPAD       65536

typedef unsigned long long ull;

// ---------------- device scratch ----------------
__device__ float g_P[NUM_TOKENS * 3072];   // [tok][0:1024)=H1a, [1024:2048)=H1b, [2048:3072)=HD
__device__ float g_tok_att[NUM_TOKENS];
__device__ float g_prior[MAXW];
__device__ float g_Cw[MAXW * UNARY];
__device__ float g_probs[NUM_CAND * MAXW];
__device__ ull   g_keys[NPAD];
__device__ float g_scores[NUM_CAND];
__device__ int   g_sorted_se[NUM_CAND];
__device__ int   g_pidx[NTOP];
__device__ int   g_hist[NUM_TOKENS];
__device__ int   g_base[NUM_TOKENS];
__device__ int   g_perm[NUM_CAND];

// ---------------- f32x2 packed helpers ----------------
__device__ __forceinline__ ull pack2(float lo, float hi) {
    ull r; asm("mov.b64 %0, {%1, %2};" : "=l"(r) : "f"(lo), "f"(hi)); return r;
}
__device__ __forceinline__ ull fma2(ull a, ull b, ull c) {
    ull d; asm("fma.rn.f32x2 %0, %1, %2, %3;" : "=l"(d) : "l"(a), "l"(b), "l"(c)); return d;
}
__device__ __forceinline__ float2 unpack2(ull v) {
    float2 f; asm("mov.b64 {%0, %1}, %2;" : "=f"(f.x), "=f"(f.y) : "l"(v)); return f;
}

// ---------------- combined zero: g_hist + key padding ----------------
__global__ void zero_kernel() {
    int i = blockIdx.x * 256 + threadIdx.x;     // 96*256 = 24576 threads
    if (i < NUM_TOKENS) g_hist[i] = 0;
    if (i < NPAD - NUM_CAND) g_keys[NUM_CAND + i] = ~0ull;
}

// ---------------- tok_att = hidden @ w_attn + b_attn ----------------
__global__ void tok_att_kernel(const float* __restrict__ hid,
                               const float* __restrict__ w,
                               const float* __restrict__ b) {
    int warp = (blockIdx.x * blockDim.x + threadIdx.x) >> 5;
    int lane = threadIdx.x & 31;
    if (warp >= NUM_TOKENS) return;
    float acc = 0.f;
    for (int k = lane; k < HIDDEN; k += 32)
        acc += hid[(size_t)warp * HIDDEN + k] * w[k];
    #pragma unroll
    for (int o = 16; o; o >>= 1) acc += __shfl_down_sync(0xffffffffu, acc, o);
    if (lane == 0) g_tok_att[warp] = acc + b[0];
}

// ---------------- width tables ----------------
__global__ void tables_kernel(const float* __restrict__ ew,
                              const float* __restrict__ ewp,
                              const float* __restrict__ W1,
                              const float* __restrict__ Wp1,
                              const float* __restrict__ bp1,
                              const float* __restrict__ Wp2,
                              const float* __restrict__ bp2) {
    int w = blockIdx.x;
    int tid = threadIdx.x;
    __shared__ float red[256];
    float local = 0.f;
    for (int u = tid; u < UNARY; u += 256) {
        float cw = 0.f, hp = 0.f;
        #pragma unroll
        for (int f = 0; f < MAXW; f++) {
            cw += ew [w * MAXW + f] * W1 [(size_t)(1536 + f) * UNARY + u];
            hp += ewp[w * MAXW + f] * Wp1[(size_t)f * UNARY + u];
        }
        g_Cw[w * UNARY + u] = cw;
        hp += bp1[u];
        hp = fmaxf(hp, 0.f);
        local += hp * Wp2[u];
    }
    red[tid] = local;
    __syncthreads();
    for (int s = 128; s; s >>= 1) {
        if (tid < s) red[tid] += red[tid + s];
        __syncthreads();
    }
    if (tid == 0) g_prior[w] = red[0] + bp2[0];
}

// ---------------- counting-sort permutation by start ----------------
__global__ void hist_kernel(const int* __restrict__ starts) {
    int c = blockIdx.x * 256 + threadIdx.x;
    if (c < NUM_CAND) atomicAdd(&g_hist[starts[c]], 1);
}
__global__ __launch_bounds__(1024) void scan_kernel() {
    __shared__ int a[2048], b[2048];
    int t = threadIdx.x;
    a[t] = g_hist[t]; a[t + 1024] = g_hist[t + 1024];
    __syncthreads();
    int* src = a; int* dst = b;
    for (int off = 1; off < 2048; off <<= 1) {
        #pragma unroll
        for (int q = 0; q < 2; q++) {
            int i = t + q * 1024;
            dst[i] = src[i] + (i >= off ? src[i - off] : 0);
        }
        __syncthreads();
        int* tmp = src; src = dst; dst = tmp;
    }
    g_base[t]        = t ? src[t - 1] : 0;
    g_base[t + 1024] = src[t + 1023];
}
__global__ void scatter_kernel(const int* __restrict__ starts) {
    int c = blockIdx.x * 256 + threadIdx.x;
    if (c < NUM_CAND) {
        int pos = atomicAdd(&g_base[starts[c]], 1);
        g_perm[pos] = c;
    }
}

// ---------------- SGEMM half: g_P[m0..m0+1024) = hidden @ Wcat, f32x2 ----------------
#define BM 128
#define BN 128
#define BK 16
__global__ __launch_bounds__(256, 2) void sgemm_kernel(const float* __restrict__ A,
                                                       const float* __restrict__ W1,
                                                       int m0) {
    __shared__ float As[2][BK][BM];
    __shared__ float Bs[2][BK][BN];
    int bm = m0 + blockIdx.y * BM, bn = blockIdx.x * BN;
    int tid = threadIdx.x;
    int tr = tid >> 4, tc = tid & 15;

    ull accp[8][4];
    #pragma unroll
    for (int i = 0; i < 8; i++)
        #pragma unroll
        for (int j = 0; j < 4; j++) accp[i][j] = 0ull;

    int a_row = tid >> 2;
    int a_col = (tid & 3) << 2;
    int b_k   = tid >> 5;
    int b_n   = (tid & 31) << 2;

    int n_global = bn + b_n;
    int seg_off = (n_global < 1024) ? 0 : (n_global < 2048 ? 768 : 1556);
    int col = n_global & 1023;

    float4 ra0, ra1, rb0, rb1;
    ra0 = *reinterpret_cast<const float4*>(&A[(size_t)(bm + a_row) * HIDDEN + a_col]);
    ra1 = *reinterpret_cast<const float4*>(&A[(size_t)(bm + a_row + 64) * HIDDEN + a_col]);
    rb0 = *reinterpret_cast<const float4*>(&W1[(size_t)(seg_off + b_k) * UNARY + col]);
    rb1 = *reinterpret_cast<const float4*>(&W1[(size_t)(seg_off + b_k + 8) * UNARY + col]);
    {
        As[0][a_col + 0][a_row] = ra0.x; As[0][a_col + 1][a_row] = ra0.y;
        As[0][a_col + 2][a_row] = ra0.z; As[0][a_col + 3][a_row] = ra0.w;
        As[0][a_col + 0][a_row + 64] = ra1.x; As[0][a_col + 1][a_row + 64] = ra1.y;
        As[0][a_col + 2][a_row + 64] = ra1.z; As[0][a_col + 3][a_row + 64] = ra1.w;
        *reinterpret_cast<float4*>(&Bs[0][b_k][b_n]) = rb0;
        *reinterpret_cast<float4*>(&Bs[0][b_k + 8][b_n]) = rb1;
    }
    __syncthreads();

    int buf = 0;
    for (int kt = 0; kt < HIDDEN; kt += BK) {
        bool more = (kt + BK) < HIDDEN;
        if (more) {
            int kn = kt + BK;
            ra0 = *reinterpret_cast<const float4*>(&A[(size_t)(bm + a_row) * HIDDEN + kn + a_col]);
            ra1 = *reinterpret_cast<const float4*>(&A[(size_t)(bm + a_row + 64) * HIDDEN + kn + a_col]);
            rb0 = *reinterpret_cast<const float4*>(&W1[(size_t)(seg_off + kn + b_k) * UNARY + col]);
            rb1 = *reinterpret_cast<const float4*>(&W1[(size_t)(seg_off + kn + b_k + 8) * UNARY + col]);
        }
        #pragma unroll
        for (int kk = 0; kk < BK; kk++) {
            float4 a0 = *reinterpret_cast<const float4*>(&As[buf][kk][tr * 8]);
            float4 a1 = *reinterpret_cast<const float4*>(&As[buf][kk][tr * 8 + 4]);
            const ull* brow = reinterpret_cast<const ull*>(&Bs[buf][kk][tc * 8]);
            ull b0 = brow[0], b1v = brow[1], b2v = brow[2], b3v = brow[3];
            float ra[8] = {a0.x, a0.y, a0.z, a0.w, a1.x, a1.y, a1.z, a1.w};
            #pragma unroll
            for (int i = 0; i < 8; i++) {
                ull aa = pack2(ra[i], ra[i]);
                accp[i][0] = fma2(aa, b0,  accp[i][0]);
                accp[i][1] = fma2(aa, b1v, accp[i][1]);
                accp[i][2] = fma2(aa, b2v, accp[i][2]);
                accp[i][3] = fma2(aa, b3v, accp[i][3]);
            }
        }
        if (more) {
            int nb = buf ^ 1;
            As[nb][a_col + 0][a_row] = ra0.x; As[nb][a_col + 1][a_row] = ra0.y;
            As[nb][a_col + 2][a_row] = ra0.z; As[nb][a_col + 3][a_row] = ra0.w;
            As[nb][a_col + 0][a_row + 64] = ra1.x; As[nb][a_col + 1][a_row + 64] = ra1.y;
            As[nb][a_col + 2][a_row + 64] = ra1.z; As[nb][a_col + 3][a_row + 64] = ra1.w;
            *reinterpret_cast<float4*>(&Bs[nb][b_k][b_n]) = rb0;
            *reinterpret_cast<float4*>(&Bs[nb][b_k + 8][b_n]) = rb1;
            __syncthreads();
            buf = nb;
        }
    }
    #pragma unroll
    for (int i = 0; i < 8; i++) {
        float2 v0 = unpack2(accp[i][0]), v1 = unpack2(accp[i][1]);
        float2 v2 = unpack2(accp[i][2]), v3 = unpack2(accp[i][3]);
        float4 w0 = make_float4(v0.x, v0.y, v1.x, v1.y);
        float4 w1 = make_float4(v2.x, v2.y, v3.x, v3.y);
        size_t rowoff = (size_t)(bm + tr * 8 + i) * 3072 + bn + tc * 8;
        *reinterpret_cast<float4*>(&g_P[rowoff])     = w0;
        *reinterpret_cast<float4*>(&g_P[rowoff + 4]) = w1;
    }
}

// ---------------- softmax probs: one warp per candidate ----------------
__global__ __launch_bounds__(256) void p_kernel(const int* __restrict__ starts,
                                                const int* __restrict__ ends) {
    int c = blockIdx.x * 8 + (threadIdx.x >> 5);
    int lane = threadIdx.x & 31;
    if (c >= NUM_CAND) return;
    int s = starts[c], e = ends[c];
    int wi = e - s;
    float l = (lane <= wi) ? g_tok_att[s + lane] : __int_as_float(0xff800000);
    float m = l;
    #pragma unroll
    for (int o = 16; o; o >>= 1) m = fmaxf(m, __shfl_xor_sync(0xffffffffu, m, o));
    float ex = (lane <= wi) ? expf(l - m) : 0.f;
    float sm = ex;
    #pragma unroll
    for (int o = 16; o; o >>= 1) sm += __shfl_xor_sync(0xffffffffu, sm, o);
    if (lane < MAXW) g_probs[c * MAXW + lane] = (lane <= wi) ? (ex / sm) : 0.f;
}

// ---------------- span_emb rows (perm order, streaming stores) ----------------
__global__ __launch_bounds__(192) void emb_kernel(const float* __restrict__ hid,
                                                  const int* __restrict__ starts,
                                                  const int* __restrict__ ends,
                                                  const float* __restrict__ ew,
                                                  float* __restrict__ out) {
    int c = g_perm[blockIdx.x];
    int tid = threadIdx.x;
    int s = starts[c], e = ends[c];
    int wi = e - s;

    __shared__ float p[MAXW];
    if (tid < MAXW) p[tid] = g_probs[c * MAXW + tid];
    __syncthreads();

    float4* row4 = reinterpret_cast<float4*>(out + (size_t)c * SPAN_DIM);
    const float4* hid4 = reinterpret_cast<const float4*>(hid);

    float4 acc = make_float4(0.f, 0.f, 0.f, 0.f);
    for (int i = 0; i <= wi; i++) {
        float4 v = hid4[(size_t)(s + i) * 192 + tid];
        if (i == 0)  __stcs(&row4[tid], v);
        if (i == wi) __stcs(&row4[192 + tid], v);
        float pi = p[i];
        acc.x += pi * v.x; acc.y += pi * v.y; acc.z += pi * v.z; acc.w += pi * v.w;
    }
    __stcs(&row4[389 + tid], acc);
    if (tid < 5) {
        float4 w = reinterpret_cast<const float4*>(ew)[wi * 5 + tid];
        __stcs(&row4[384 + tid], w);
    }
}

// ---------------- score half: lo handles e<1024, hi handles e>=1024 ----------------
__global__ __launch_bounds__(256) void score_kernel(const int* __restrict__ starts,
                                                    const int* __restrict__ ends,
                                                    const float* __restrict__ b1,
                                                    const float* __restrict__ W2,
                                                    const float* __restrict__ b2v,
                                                    int hi) {
    int slot = blockIdx.x * 8 + (threadIdx.x >> 5);
    int lane = threadIdx.x & 31;
    if (slot >= NUM_CAND) return;
    int c = g_perm[slot];
    int s = starts[c], e = ends[c];
    if ((e >= 1024) != (hi != 0)) return;
    int wi = e - s;

    float pv = (lane <= wi) ? g_probs[c * MAXW + lane] : 0.f;

    const float4* pa  = reinterpret_cast<const float4*>(&g_P[(size_t)s * 3072]);
    const float4* pb  = reinterpret_cast<const float4*>(&g_P[(size_t)e * 3072 + 1024]);
    const float4* pcw = reinterpret_cast<const float4*>(&g_Cw[wi * UNARY]);
    const float4* pb1 = reinterpret_cast<const float4*>(b1);

    float4 acc[8];
    #pragma unroll
    for (int j = 0; j < 8; j++) {
        int idx = j * 32 + lane;
        float4 a = pa[idx], b = pb[idx], cw = pcw[idx], bb = pb1[idx];
        acc[j].x = a.x + b.x + cw.x + bb.x;
        acc[j].y = a.y + b.y + cw.y + bb.y;
        acc[j].z = a.z + b.z + cw.z + bb.z;
        acc[j].w = a.w + b.w + cw.w + bb.w;
    }
    for (int i = 0; i <= wi; i++) {
        float pi = __shfl_sync(0xffffffffu, pv, i);
        const float4* hd = reinterpret_cast<const float4*>(&g_P[(size_t)(s + i) * 3072 + 2048]);
        #pragma unroll
        for (int j = 0; j < 8; j++) {
            float4 v = hd[j * 32 + lane];
            acc[j].x += pi * v.x; acc[j].y += pi * v.y;
            acc[j].z += pi * v.z; acc[j].w += pi * v.w;
        }
    }
    const float4* W2_4 = reinterpret_cast<const float4*>(W2);
    float local = 0.f;
    #pragma unroll
    for (int j = 0; j < 8; j++) {
        float4 w = W2_4[j * 32 + lane];
        local += fmaxf(acc[j].x, 0.f) * w.x + fmaxf(acc[j].y, 0.f) * w.y
               + fmaxf(acc[j].z, 0.f) * w.z + fmaxf(acc[j].w, 0.f) * w.w;
    }
    #pragma unroll
    for (int o = 16; o; o >>= 1) local += __shfl_xor_sync(0xffffffffu, local, o);
    if (lane == 0) {
        float sc = local + b2v[0] + g_prior[wi];
        g_scores[c] = sc;
        unsigned u = __float_as_uint(sc);
        u = (u & 0x80000000u) ? ~u : (u | 0x80000000u);
        g_keys[c] = ((ull)(~u) << 32) | (unsigned)c;
    }
}

// ---------------- bitonic sort, 4096-element smem chunks ----------------
__global__ __launch_bounds__(1024) void bitonic_smem_full4k() {
    __shared__ ull sk[4096];
    int base = blockIdx.x * 4096, t = threadIdx.x;
    #pragma unroll
    for (int r = 0; r < 4; r++) sk[t + r * 1024] = g_keys[base + t + r * 1024];
    __syncthreads();
    for (int k = 2; k <= 4096; k <<= 1)
        for (int j = k >> 1; j > 0; j >>= 1) {
            #pragma unroll
            for (int q = 0; q < 2; q++) {
                int pI = t + q * 1024;
                int i = ((pI & ~(j - 1)) << 1) | (pI & (j - 1));
                bool dir = (((base + i) & k) == 0);
                ull a = sk[i], b = sk[i | j];
                if ((a > b) == dir) { sk[i] = b; sk[i | j] = a; }
            }
            __syncthreads();
        }
    #pragma unroll
    for (int r = 0; r < 4; r++) g_keys[base + t + r * 1024] = sk[t + r * 1024];
}

__global__ __launch_bounds__(1024) void bitonic_smem_tail4k(int k) {
    __shared__ ull sk[4096];
    int base = blockIdx.x * 4096, t = threadIdx.x;
    #pragma unroll
    for (int r = 0; r < 4; r++) sk[t + r * 1024] = g_keys[base + t + r * 1024];
    __syncthreads();
    for (int j = 2048; j > 0; j >>= 1) {
        #pragma unroll
        for (int q = 0; q < 2; q++) {
            int pI = t + q * 1024;
            int i = ((pI & ~(j - 1)) << 1) | (pI & (j - 1));
            bool dir = (((base + i) & k) == 0);
            ull a = sk[i], b = sk[i | j];
            if ((a > b) == dir) { sk[i] = b; sk[i | j] = a; }
        }
        __syncthreads();
    }
    #pragma unroll
    for (int r = 0; r < 4; r++) g_keys[base + t + r * 1024] = sk[t + r * 1024];
}

__global__ void bitonic_gstep(int j, int k) {
    int pI = blockIdx.x * blockDim.x + threadIdx.x;
    int i = ((pI & ~(j - 1)) << 1) | (pI & (j - 1));
    bool dir = ((i & k) == 0);
    ull a = g_keys[i], b = g_keys[i | j];
    if ((a > b) == dir) { g_keys[i] = b; g_keys[i | j] = a; }
}

__global__ void decorate_kernel(const int* __restrict__ starts,
                                const int* __restrict__ ends) {
    int pI = blockIdx.x * blockDim.x + threadIdx.x;
    if (pI < NUM_CAND) {
        int idx = (int)(g_keys[pI] & 0xffffffffull);
        g_sorted_se[pI] = (starts[idx] << 16) | ends[idx];
    }
}

// ---------------- serial greedy NMS + position sort + scalar outputs ----------------
__global__ __launch_bounds__(256) void nms_kernel(const int* __restrict__ starts,
                                                  const int* __restrict__ ends,
                                                  const int* __restrict__ spk,
                                                  float* __restrict__ out) {
    __shared__ int latest[NUM_TOKENS];
    __shared__ int earliest[NUM_TOKENS];
    __shared__ int chunk[2048];
    __shared__ ull akey[NTOP];
    __shared__ int aidx[NTOP];
    __shared__ int s_count;

    int tid = threadIdx.x, lane = tid & 31;
    for (int t = tid; t < NUM_TOKENS; t += 256) { latest[t] = -1; earliest[t] = NUM_TOKENS; }
    if (tid == 0) s_count = 0;
    __syncthreads();

    int count = 0, pos = 0;
    while (pos < NUM_CAND && count < NTOP) {
        int n = min(2048, NUM_CAND - pos);
        for (int t = tid; t < n; t += 256) chunk[t] = g_sorted_se[pos + t];
        __syncthreads();
        if (tid < 32) {
            for (int cI = 0; cI < n && count < NTOP; cI++) {
                int se = chunk[cI];
                int s = se >> 16, e = se & 0xffff;
                int t = s + lane;
                bool act = (lane <= e - s);
                bool c1 = act && (t > s) && (latest[t] > e);
                bool c2 = act && (t < e) && (earliest[t] < s);
                if (__ballot_sync(0xffffffffu, c1 || c2) == 0u) {
                    if (lane == 0) {
                        latest[s] = max(latest[s], e);
                        earliest[e] = min(earliest[e], s);
                        int idx = (int)(g_keys[pos + cI] & 0xffffffffull);
                        aidx[count] = idx;
                        akey[count] = (((ull)(s * (NUM_TOKENS + 1) + e)) << 10) | (unsigned)count;
                    }
                    count++;
                }
                __syncwarp();
            }
            if (lane == 0) s_count = count;
        }
        __syncthreads();
        count = s_count;
        pos += n;
    }
    __syncthreads();
    for (int r = tid; r < NTOP; r += 256)
        if (r >= count) { akey[r] = ~0ull; aidx[r] = 0; }
    __syncthreads();

    for (int k = 2; k <= NTOP; k <<= 1)
        for (int j = k >> 1; j > 0; j >>= 1) {
            int i = ((tid & ~(j - 1)) << 1) | (tid & (j - 1));
            bool dir = ((i & k) == 0);
            ull a = akey[i], b = akey[i | j];
            if ((a > b) == dir) {
                akey[i] = b; akey[i | j] = a;
                int x = aidx[i]; aidx[i] = aidx[i | j]; aidx[i | j] = x;
            }
            __syncthreads();
        }

    int first = aidx[0];
    const size_t base = (size_t)NUM_CAND * SPAN_DIM;
    const size_t emb_off = base + 3 * NTOP;
    const size_t sc_off = emb_off + (size_t)NTOP * SPAN_DIM;
    for (int r = tid; r < NTOP; r += 256) {
        int idx = (r < count) ? aidx[r] : first;
        int s = starts[idx], e = ends[idx];
        out[base + r]            = (float)idx;
        out[base + NTOP + r]     = (float)s;
        out[base + 2 * NTOP + r] = (float)e;
        out[sc_off + r]          = g_scores[idx];
        out[sc_off + NTOP + r]   = (float)spk[s];
        g_pidx[r] = idx;
    }
}

__global__ void gather_emb(float* __restrict__ out) {
    int r = blockIdx.x;
    int idx = g_pidx[r];
    const float* src = out + (size_t)idx * SPAN_DIM;
    float* dst = out + (size_t)NUM_CAND * SPAN_DIM + 3 * NTOP + (size_t)r * SPAN_DIM;
    for (int d = threadIdx.x; d < SPAN_DIM; d += 256) dst[d] = src[d];
}

// ---------------- launch (multi-stream, graph-capturable fork/join) ----------------
extern "C" void kernel_launch(void* const* d_in, const int* in_sizes, int n_in,
                              void* d_out, int out_size) {
    const float* hid    = (const float*)d_in[0];
    const int*   starts = (const int*)  d_in[1];
    const int*   ends   = (const int*)  d_in[2];
    const int*   spk    = (const int*)  d_in[3];
    const float* w_attn = (const float*)d_in[4];
    const float* b_attn = (const float*)d_in[5];
    const float* W1     = (const float*)d_in[6];
    const float* b1     = (const float*)d_in[7];
    const float* W2     = (const float*)d_in[8];
    const float* b2     = (const float*)d_in[9];
    const float* ew     = (const float*)d_in[10];
    const float* ewp    = (const float*)d_in[11];
    const float* Wp1    = (const float*)d_in[12];
    const float* bp1    = (const float*)d_in[13];
    const float* Wp2    = (const float*)d_in[14];
    const float* bp2    = (const float*)d_in[15];
    float* out = (float*)d_out;

    static cudaStream_t sB = 0, sC = 0;
    static cudaEvent_t evRoot = 0, evGL = 0, evGH = 0, evSetup = 0, evEmb = 0, evScore = 0;
    if (!sB) {
        cudaStreamCreateWithFlags(&sB, cudaStreamNonBlocking);
        cudaStreamCreateWithFlags(&sC, cudaStreamNonBlocking);
        cudaEventCreateWithFlags(&evRoot,  cudaEventDisableTiming);
        cudaEventCreateWithFlags(&evGL,    cudaEventDisableTiming);
        cudaEventCreateWithFlags(&evGH,    cudaEventDisableTiming);
        cudaEventCreateWithFlags(&evSetup, cudaEventDisableTiming);
        cudaEventCreateWithFlags(&evEmb,   cudaEventDisableTiming);
        cudaEventCreateWithFlags(&evScore, cudaEventDisableTiming);
    }

    // fork from capture-origin (default) stream
    cudaEventRecord(evRoot, 0);
    cudaStreamWaitEvent(sB, evRoot, 0);
    cudaStreamWaitEvent(sC, evRoot, 0);

    // setup chain on sB
    zero_kernel<<<96, 256, 0, sB>>>();
    tok_att_kernel<<<256, 256, 0, sB>>>(hid, w_attn, b_attn);
    tables_kernel<<<20, 256, 0, sB>>>(ew, ewp, W1, Wp1, bp1, Wp2, bp2);
    hist_kernel<<<160, 256, 0, sB>>>(starts);
    scan_kernel<<<1, 1024, 0, sB>>>();

    // sgemm halves on default stream (slot 6 for ncu)
    sgemm_kernel<<<dim3(24, 8), 256>>>(hid, W1, 0);
    cudaEventRecord(evGL, 0);
    sgemm_kernel<<<dim3(24, 8), 256>>>(hid, W1, 1024);
    cudaEventRecord(evGH, 0);

    // rest of setup + emb on sB
    scatter_kernel<<<160, 256, 0, sB>>>(starts);
    p_kernel<<<NUM_CAND / 8, 256, 0, sB>>>(starts, ends);
    cudaEventRecord(evSetup, sB);
    emb_kernel<<<NUM_CAND, 192, 0, sB>>>(hid, starts, ends, ew, out);
    cudaEventRecord(evEmb, sB);

    // score halves on sC, pipelined against sgemm_hi
    cudaStreamWaitEvent(sC, evSetup, 0);
    cudaStreamWaitEvent(sC, evGL, 0);
    score_kernel<<<NUM_CAND / 8, 256, 0, sC>>>(starts, ends, b1, W2, b2, 0);
    cudaStreamWaitEvent(sC, evGH, 0);
    score_kernel<<<NUM_CAND / 8, 256, 0, sC>>>(starts, ends, b1, W2, b2, 1);
    cudaEventRecord(evScore, sC);

    // join on default stream: sort -> nms -> gather
    cudaStreamWaitEvent(0, evScore, 0);
    bitonic_smem_full4k<<<16, 1024>>>();
    for (int k = 8192; k <= 65536; k <<= 1) {
        for (int j = k >> 1; j >= 4096; j >>= 1)
            bitonic_gstep<<<128, 256>>>(j, k);
        bitonic_smem_tail4k<<<16, 1024>>>(k);
    }
    decorate_kernel<<<160, 256>>>(starts, ends);
    nms_kernel<<<1, 256>>>(starts, ends, spk, out);
    cudaStreamWaitEvent(0, evEmb, 0);
    gather_emb<<<NTOP, 256>>>(out);
}